// round 12
// baseline (speedup 1.0000x reference)
#include <cuda_runtime.h>
#include <math.h>

// DTW 2048x2048, 4-CTA x 4-warp free-running anti-diagonal block pipeline.
//
// R11 change vs R7: the per-step __syncthreads convoy is gone. Each warp
// free-runs over its 128 blocks; synchronization is pure data-flow:
//  - intra-CTA: smem ring (NBUF=4 slots) + monotonic counters. Producer
//    lane31 st.release's sflag[w+1]=q+1 after the block's 32 STS; consumer
//    lanes spin on ld.acquire (asm volatile, un-hoistable). Backpressure
//    via scons[w] (consumed count), only checked for q >= NBUF.
//  - inter-CTA: unchanged data-as-flag sentinel global buffer (reset to -1
//    by a pre-kernel each launch) + one-block register prefetch.
// Compute core unchanged: thread t of CTA c owns rows c*512+t*4..+3 in
// registers, b[]/a[] roles alternate per diagonal, y padded with BIGV so
// out-of-range cells self-poison.

#define LEN    2048
#define C      4
#define NT     128
#define NW     4
#define RPT    4                  // C*NT*RPT == LEN
#define BD     32                 // diagonals per block
#define NBLK   128                // covers d = 1..4096 (>= 4094)
#define NBUF   4                  // smem ring depth (power of 2)
#define BIGV   1e19f
#define SENT   -1.0f
#define OFF    2047
#define YPSZ   6144

__device__ float g_bound[C][NBLK][BD];

__global__ void reset_bound_kernel()
{
    int i = blockIdx.x * blockDim.x + threadIdx.x;
    if (i < C * NBLK * BD) ((float*)g_bound)[i] = SENT;
}

// ---- un-hoistable sync primitives ----
__device__ __forceinline__ float ld_cg_volatile(const float* p)
{
    float v;
    asm volatile("ld.global.cg.f32 %0, [%1];" : "=f"(v) : "l"(p) : "memory");
    return v;
}
__device__ __forceinline__ void st_cg(float* p, float v)
{
    asm volatile("st.global.cg.f32 [%0], %1;" :: "l"(p), "f"(v));
}
__device__ __forceinline__ unsigned ld_acq_shared(const unsigned* p)
{
    unsigned v;
    unsigned a = (unsigned)__cvta_generic_to_shared(p);
    asm volatile("ld.acquire.cta.shared.u32 %0, [%1];" : "=r"(v) : "r"(a) : "memory");
    return v;
}
__device__ __forceinline__ void st_rel_shared(unsigned* p, unsigned v)
{
    unsigned a = (unsigned)__cvta_generic_to_shared(p);
    asm volatile("st.release.cta.shared.u32 [%0], %1;" :: "r"(a), "r"(v) : "memory");
}

__global__ __launch_bounds__(NT, 1)
void dtw_wavefront(const float* __restrict__ x,
                   const float* __restrict__ y,
                   float* __restrict__ out)
{
    __shared__ float    ypad[YPSZ];
    __shared__ float    sbuf[NW][NBUF][BD];  // indexed by CONSUMER warp
    __shared__ float    sdummy[BD];          // sink for last warp
    __shared__ unsigned sflag[NW];           // blocks published to warp w
    __shared__ unsigned scons[NW];           // blocks consumed by warp w

    const int tid  = threadIdx.x;
    const int lane = tid & 31;
    const int warp = tid >> 5;
    const int cta  = blockIdx.x;

    for (int idx = tid; idx < YPSZ; idx += NT) {
        int j = idx - OFF;
        ypad[idx] = (j >= 0 && j < LEN) ? y[j] : BIGV;
    }
    if (tid < NW) { sflag[tid] = 0; scons[tid] = 0; }
    __syncthreads();                       // the only CTA-wide barrier

    const int r0 = cta * (NT * RPT) + tid * RPT;

    float xs[RPT];
#pragma unroll
    for (int k = 0; k < RPT; k++) xs[k] = x[r0 + k];

    float b[RPT], a[RPT];
#pragma unroll
    for (int k = 0; k < RPT; k++) { b[k] = BIGV; a[k] = BIGV; }
    if (cta == 0 && tid == 0) {
        float c00 = xs[0] - ypad[OFF];
        b[0] = c00 * c00;
    }

    float cb = BIGV, ca = BIGV;
    const bool isl0  = (lane == 0);
    const bool isl31 = (lane == 31);
    const bool wlast = (cta == C - 1 && tid == NT - 1);
    const bool gcons = (warp == 0 && cta > 0);       // consumes from global
    const bool scon  = (warp > 0);                   // consumes from smem
    const bool sprod = (warp < NW - 1);              // produces to smem
    const bool gprod = (warp == NW - 1 && cta < C - 1); // produces to global

    float e[BD], en[BD];
#pragma unroll
    for (int i = 0; i < BD; i++) { e[i] = BIGV; en[i] = BIGV; }

    // Prefetch block 0's upstream boundary (validated at q=0).
    if (gcons) {
        const float4* gp = (const float4*)&g_bound[cta - 1][0][0];
#pragma unroll
        for (int c4 = 0; c4 < BD / 4; c4++) {
            float4 v = __ldcg(gp + c4);
            e[c4 * 4 + 0] = v.x; e[c4 * 4 + 1] = v.y;
            e[c4 * 4 + 2] = v.z; e[c4 * 4 + 3] = v.w;
        }
    }

    for (int q = 0; q < NBLK; q++) {
        const int d0   = 1 + q * BD;
        const int slot = q & (NBUF - 1);
        const bool qlast = (q == NBLK - 1);

        // ---- acquire upstream boundary e[] for block q ----
        if (gcons) {
            // prefetch q+1 (unchecked), then validate q's prefetched values
            if (q + 1 < NBLK) {
                const float4* gp = (const float4*)&g_bound[cta - 1][q + 1][0];
#pragma unroll
                for (int c4 = 0; c4 < BD / 4; c4++) {
                    float4 v = __ldcg(gp + c4);
                    en[c4 * 4 + 0] = v.x; en[c4 * 4 + 1] = v.y;
                    en[c4 * 4 + 2] = v.z; en[c4 * 4 + 3] = v.w;
                }
            }
            const float* src = &g_bound[cta - 1][q][0];
#pragma unroll
            for (int i = 0; i < BD; i++) {
                if (e[i] < 0.0f) {
                    float v = ld_cg_volatile(src + i);
                    while (v < 0.0f) { __nanosleep(20); v = ld_cg_volatile(src + i); }
                    e[i] = v;
                }
            }
        } else if (scon) {
            // wait until producer published block q, then read the slot
            unsigned f;
            do { f = ld_acq_shared(&sflag[warp]); } while ((int)f < q + 1);
            const float4* sp = (const float4*)&sbuf[warp][slot][0];
#pragma unroll
            for (int c4 = 0; c4 < BD / 4; c4++) {
                float4 v = sp[c4];
                e[c4 * 4 + 0] = v.x; e[c4 * 4 + 1] = v.y;
                e[c4 * 4 + 2] = v.z; e[c4 * 4 + 3] = v.w;
            }
            __syncwarp();
            if (isl0) st_rel_shared(&scons[warp], (unsigned)(q + 1));
        }
        // cta 0 / warp 0: e stays BIGV

        // ---- y window: cell (i,k) uses yblk[RPT + i - k] ----
        float yblk[BD + RPT];
        {
            const float4* yp4 = (const float4*)&ypad[OFF + d0 - r0 - RPT];
#pragma unroll
            for (int c4 = 0; c4 < (BD + RPT) / 4; c4++) {
                float4 v = yp4[c4];
                yblk[c4 * 4 + 0] = v.x; yblk[c4 * 4 + 1] = v.y;
                yblk[c4 * 4 + 2] = v.z; yblk[c4 * 4 + 3] = v.w;
            }
        }

        // ---- backpressure: slot must have been consumed (q >= NBUF only) ----
        if (sprod && q >= NBUF) {
            unsigned f;
            do { f = ld_acq_shared(&scons[warp + 1]); }
            while ((int)f < q - NBUF + 1);
        }

        float* sp = sprod ? &sbuf[warp + 1][slot][0] : sdummy;
        float* gq = &g_bound[cta][q][0];

        float nb_prev = __shfl_up_sync(0xffffffffu, a[RPT - 1], 1);

#define DIAG_STEP(I, P, Q) do {                                            \
        float nbb = __shfl_up_sync(0xffffffffu, P[RPT - 1], 1);            \
        float up0 = isl0 ? ((I) >= 1 ? e[(I) - 1] : cb) : nbb;             \
        float dg0 = isl0 ? ((I) >= 2 ? e[(I) - 2]                          \
                                     : ((I) == 1 ? cb : ca))               \
                         : nb_prev;                                        \
        nb_prev = nbb;                                                     \
        _Pragma("unroll")                                                  \
        for (int k = RPT - 1; k >= 0; k--) {                               \
            float up = (k == 0) ? up0 : P[k - 1];                          \
            float dg = (k == 0) ? dg0 : Q[k - 1];                          \
            float cc = xs[k] - yblk[RPT + (I) - k];                        \
            Q[k] = fmaf(cc, cc, fminf(fminf(up, P[k]), dg));               \
        }                                                                  \
        if (isl31) {                                                       \
            sp[(I)] = Q[RPT - 1];                                          \
            if (gprod) st_cg(gq + (I), Q[RPT - 1]);                        \
        }                                                                  \
        if ((I) == 29) {                                                   \
            if (qlast && wlast) out[0] = sqrtf(Q[RPT - 1]);                \
        }                                                                  \
    } while (0)

#define DIAG_PAIR(I) DIAG_STEP(I, b, a); DIAG_STEP((I) + 1, a, b)

        DIAG_PAIR(0);  DIAG_PAIR(2);  DIAG_PAIR(4);  DIAG_PAIR(6);
        DIAG_PAIR(8);  DIAG_PAIR(10); DIAG_PAIR(12); DIAG_PAIR(14);
        DIAG_PAIR(16); DIAG_PAIR(18); DIAG_PAIR(20); DIAG_PAIR(22);
        DIAG_PAIR(24); DIAG_PAIR(26); DIAG_PAIR(28); DIAG_PAIR(30);

#undef DIAG_PAIR
#undef DIAG_STEP

        // publish to downstream warp (release orders the 32 STS above)
        if (sprod && isl31) st_rel_shared(&sflag[warp + 1], (unsigned)(q + 1));

        // carries for next block, then rotate global prefetch buffer
        ca = e[BD - 2];
        cb = e[BD - 1];
        if (gcons) {
#pragma unroll
            for (int i = 0; i < BD; i++) e[i] = en[i];
        }
    }
}

extern "C" void kernel_launch(void* const* d_in, const int* in_sizes, int n_in,
                              void* d_out, int out_size)
{
    const float* x = (const float*)d_in[0];
    const float* y = (const float*)d_in[1];
    float* out = (float*)d_out;
    (void)in_sizes; (void)n_in; (void)out_size;
    reset_bound_kernel<<<32, 512>>>();
    dtw_wavefront<<<C, NT>>>(x, y, out);
}

// round 15
// speedup vs baseline: 2.7643x; 2.7643x over previous
#include <cuda_runtime.h>
#include <math.h>

// DTW 2048x2048, 2-CTA x 8-warp skewed anti-diagonal block pipeline.
//
// R12: revert to the R7 barrier skeleton (R11's free-running dataflow spun
// ~2.2x extra instructions and regressed). Change vs R7: C=4x4 -> C=2x8.
// With 8 warps/CTA, warps w and w+4 share an SMSP but are 4 pipeline
// stages apart -> two independent instruction streams per SMSP, hiding the
// per-diagonal shfl/min-chain latency that capped R7 at issue=24%. Also
// only ONE inter-CTA global handoff remains (cta0 warp7 -> cta1 warp0).
//
// Design recap:
//  - Thread t of CTA c owns rows c*1024 + t*4..+3 in registers; b[]/a[]
//    roles alternate per diagonal (no rotation MOVs).
//  - BD=32 diagonals per block; stage(c,w) = 9c + w; warp w handles block
//    q at step s = q + stage; one __syncthreads per step.
//  - Intra-CTA handoff: double-buffered smem rows (lane31 -> next warp).
//  - Inter-CTA handoff: data-as-flag sentinel global buffer (reset to -1
//    by a pre-kernel) + one-block register prefetch; straggler re-poll via
//    un-hoistable asm-volatile ld.global.cg + nanosleep.
//  - y padded with BIGV so out-of-range cells self-poison (no predication).

#define LEN    2048
#define C      2
#define NT     256
#define NW     8
#define RPT    4                  // C*NT*RPT == LEN
#define BD     32                 // diagonals per block
#define NBLK   128                // covers d = 1..4096 (>= 4094)
#define NSTAGE ((C - 1) * (NW + 1) + (NW - 1))   // 16
#define NSTEPS (NBLK + NSTAGE)                   // 144
#define BIGV   1e19f
#define SENT   -1.0f
#define OFF    2047
#define YPSZ   6144

__device__ float g_bound[C][NBLK][BD];

__global__ void reset_bound_kernel()
{
    int i = blockIdx.x * blockDim.x + threadIdx.x;
    if (i < C * NBLK * BD) ((float*)g_bound)[i] = SENT;
}

// Un-hoistable L2 load for the poll loop.
__device__ __forceinline__ float ld_cg_volatile(const float* p)
{
    float v;
    asm volatile("ld.global.cg.f32 %0, [%1];" : "=f"(v) : "l"(p) : "memory");
    return v;
}

__global__ __launch_bounds__(NT, 1)
void dtw_wavefront(const float* __restrict__ x,
                   const float* __restrict__ y,
                   float* __restrict__ out)
{
    __shared__ float ypad[YPSZ];
    __shared__ float bdry[2][NW][BD];   // [parity][consumer warp][diag]

    const int tid  = threadIdx.x;
    const int lane = tid & 31;
    const int warp = tid >> 5;
    const int cta  = blockIdx.x;

    for (int idx = tid; idx < YPSZ; idx += NT) {
        int j = idx - OFF;
        ypad[idx] = (j >= 0 && j < LEN) ? y[j] : BIGV;
    }
    __syncthreads();

    const int r0 = cta * (NT * RPT) + tid * RPT;

    float xs[RPT];
#pragma unroll
    for (int k = 0; k < RPT; k++) xs[k] = x[r0 + k];

    // State: b = diag d0-1, a = diag d0-2. Only (0,0) finite after diag 0.
    float b[RPT], a[RPT];
#pragma unroll
    for (int k = 0; k < RPT; k++) { b[k] = BIGV; a[k] = BIGV; }
    if (cta == 0 && tid == 0) {
        float c00 = xs[0] - ypad[OFF];
        b[0] = c00 * c00;
    }

    float cb = BIGV, ca = BIGV;     // lane0 carries: upstream bottom b at d0-1, d0-2
    const int  stage = cta * (NW + 1) + warp;
    const bool isl0  = (lane == 0);
    const bool isl31 = (lane == 31);
    const bool wlast = (cta == C - 1 && tid == NT - 1);
    const bool gcons = (warp == 0 && cta > 0);        // global consumer

    // Upstream boundary registers. For cta 0 / warp 0 these stay BIGV forever.
    float e[BD], en[BD];
#pragma unroll
    for (int i = 0; i < BD; i++) { e[i] = BIGV; en[i] = BIGV; }

    for (int s = 0; s < NSTEPS; s++) {
        const int q = s - stage;
        const bool active = (q >= 0 && q < NBLK);

        // ---- prefetch next block's global boundary (unchecked) ----
        if (gcons) {
            const int qn = q + 1;
            if (qn >= 0 && qn < NBLK) {
                const float4* gp = (const float4*)&g_bound[cta - 1][qn][0];
#pragma unroll
                for (int c4 = 0; c4 < BD / 4; c4++) {
                    float4 v = __ldcg(gp + c4);
                    en[c4 * 4 + 0] = v.x; en[c4 * 4 + 1] = v.y;
                    en[c4 * 4 + 2] = v.z; en[c4 * 4 + 3] = v.w;
                }
            }
        }

        if (active) {
            const int wpar  = s & 1;
            const int rpar  = wpar ^ 1;
            const int d0    = 1 + q * BD;
            const bool qlast = (q == NBLK - 1);

            // ---- obtain boundary e[i] = upstream bottom-row b at diag d0+i ----
            if (warp == 0) {
                if (cta > 0) {
                    // validate prefetched values; re-poll rare stragglers
                    const float* src = &g_bound[cta - 1][q][0];
#pragma unroll
                    for (int i = 0; i < BD; i++) {
                        if (e[i] < 0.0f) {
                            float v = ld_cg_volatile(src + i);
                            while (v < 0.0f) {
                                __nanosleep(20);
                                v = ld_cg_volatile(src + i);
                            }
                            e[i] = v;
                        }
                    }
                }
                // cta == 0: e stays BIGV
            } else {
                const float4* sp = (const float4*)&bdry[rpar][warp][0];
#pragma unroll
                for (int c4 = 0; c4 < BD / 4; c4++) {
                    float4 v = sp[c4];
                    e[c4 * 4 + 0] = v.x; e[c4 * 4 + 1] = v.y;
                    e[c4 * 4 + 2] = v.z; e[c4 * 4 + 3] = v.w;
                }
            }

            // ---- y window: cell (i,k) uses yblk[RPT + i - k] ----
            float yblk[BD + RPT];
            {
                const float4* yp4 = (const float4*)&ypad[OFF + d0 - r0 - RPT];
#pragma unroll
                for (int c4 = 0; c4 < (BD + RPT) / 4; c4++) {
                    float4 v = yp4[c4];
                    yblk[c4 * 4 + 0] = v.x; yblk[c4 * 4 + 1] = v.y;
                    yblk[c4 * 4 + 2] = v.z; yblk[c4 * 4 + 3] = v.w;
                }
            }

            // ---- publish target (generic volatile: smem or gmem) ----
            volatile float* bp;
            if (warp < NW - 1)       bp = &bdry[wpar][warp + 1][0];
            else if (cta < C - 1)    bp = &g_bound[cta][q][0];
            else                     bp = &bdry[wpar][0][0];   // dummy sink

            float nb_prev = __shfl_up_sync(0xffffffffu, a[RPT - 1], 1);

#define DIAG_STEP(I, P, Q) do {                                            \
            float nbb = __shfl_up_sync(0xffffffffu, P[RPT - 1], 1);        \
            float up0 = isl0 ? ((I) >= 1 ? e[(I) - 1] : cb) : nbb;         \
            float dg0 = isl0 ? ((I) >= 2 ? e[(I) - 2]                      \
                                         : ((I) == 1 ? cb : ca))           \
                             : nb_prev;                                    \
            nb_prev = nbb;                                                 \
            _Pragma("unroll")                                              \
            for (int k = RPT - 1; k >= 0; k--) {                           \
                float up = (k == 0) ? up0 : P[k - 1];                      \
                float dg = (k == 0) ? dg0 : Q[k - 1];                      \
                float cc = xs[k] - yblk[RPT + (I) - k];                    \
                Q[k] = fmaf(cc, cc, fminf(fminf(up, P[k]), dg));           \
            }                                                              \
            if (isl31) bp[(I)] = Q[RPT - 1];                               \
            if ((I) == 29) {                                               \
                if (qlast && wlast) out[0] = sqrtf(Q[RPT - 1]);            \
            }                                                              \
        } while (0)

#define DIAG_PAIR(I) DIAG_STEP(I, b, a); DIAG_STEP((I) + 1, a, b)

            DIAG_PAIR(0);  DIAG_PAIR(2);  DIAG_PAIR(4);  DIAG_PAIR(6);
            DIAG_PAIR(8);  DIAG_PAIR(10); DIAG_PAIR(12); DIAG_PAIR(14);
            DIAG_PAIR(16); DIAG_PAIR(18); DIAG_PAIR(20); DIAG_PAIR(22);
            DIAG_PAIR(24); DIAG_PAIR(26); DIAG_PAIR(28); DIAG_PAIR(30);

#undef DIAG_PAIR
#undef DIAG_STEP

            // carries for next block: upstream bottom at d0+BD-1, d0+BD-2
            ca = e[BD - 2];
            cb = e[BD - 1];
        }

        // rotate prefetch buffer (loads from this step have landed by now)
        if (gcons) {
#pragma unroll
            for (int i = 0; i < BD; i++) e[i] = en[i];
        }

        __syncthreads();
    }
}

extern "C" void kernel_launch(void* const* d_in, const int* in_sizes, int n_in,
                              void* d_out, int out_size)
{
    const float* x = (const float*)d_in[0];
    const float* y = (const float*)d_in[1];
    float* out = (float*)d_out;
    (void)in_sizes; (void)n_in; (void)out_size;
    reset_bound_kernel<<<32, 512>>>();
    dtw_wavefront<<<C, NT>>>(x, y, out);
}